// round 5
// baseline (speedup 1.0000x reference)
#include <cuda_runtime.h>
#include <cuda_bf16.h>
#include <cstdint>

#define FULL 0xFFFFFFFFu

__device__ __forceinline__ float2 cmul(float2 a, float2 b) {
    return make_float2(fmaf(a.x, b.x, -a.y * b.y),
                       fmaf(a.x, b.y,  a.y * b.x));
}

// ---------------------------------------------------------------------------
// Layout: one warp per token. Lane l holds amplitudes flat=(k<<5)|l, k=0..7.
// Initially wire w <-> flat bit (7-w): k2,k1,k0 = wires 0,1,2;
// lane bits f4..f0 = wires 3..7.
// ---------------------------------------------------------------------------

template<int RB>
__device__ __forceinline__ void rx_reg(float2 (&a)[8], float c, float s) {
#pragma unroll
    for (int k0 = 0; k0 < 8; ++k0) {
        if (k0 & (1 << RB)) continue;
        const int k1 = k0 | (1 << RB);
        float2 A = a[k0], B = a[k1];
        a[k0].x = fmaf(c, A.x,  s * B.y);
        a[k0].y = fmaf(c, A.y, -s * B.x);
        a[k1].x = fmaf(c, B.x,  s * A.y);
        a[k1].y = fmaf(c, B.y, -s * A.x);
    }
}

template<int B>
__device__ __forceinline__ void rx_lane(float2 (&a)[8], float c, float s) {
#pragma unroll
    for (int k = 0; k < 8; ++k) {
        float px = __shfl_xor_sync(FULL, a[k].x, 1 << B);
        float py = __shfl_xor_sync(FULL, a[k].y, 1 << B);
        float nx = fmaf(c, a[k].x,  s * py);
        float ny = fmaf(c, a[k].y, -s * px);
        a[k].x = nx; a[k].y = ny;
    }
}

template<int W>
__device__ __forceinline__ void rx_wire(float2 (&a)[8], float c, float s) {
    constexpr int B = 7 - W;
    if constexpr (B >= 5) rx_reg<B - 5>(a, c, s);
    else                  rx_lane<B>(a, c, s);
}

template<int W>
__device__ __forceinline__ void rz_wire(float2 (&a)[8], int lane, float c, float s) {
    constexpr int B = 7 - W;
#pragma unroll
    for (int k = 0; k < 8; ++k) {
        int bit;
        if constexpr (B >= 5) bit = (k >> (B - 5)) & 1;
        else                  bit = (lane >> B) & 1;
        float t = bit ? s : -s;
        float nx = fmaf(a[k].x, c, -a[k].y * t);
        float ny = fmaf(a[k].y, c,  a[k].x * t);
        a[k].x = nx; a[k].y = ny;
    }
}

template<int BC, int BT>
__device__ __forceinline__ void cnot(float2 (&a)[8], int lane) {
    if constexpr (BC >= 5 && BT >= 5) {
#pragma unroll
        for (int k = 0; k < 8; ++k) {
            if ((k & (1 << (BC - 5))) && !(k & (1 << (BT - 5)))) {
                const int k2 = k | (1 << (BT - 5));
                float2 t = a[k]; a[k] = a[k2]; a[k2] = t;
            }
        }
    } else if constexpr (BC >= 5 && BT < 5) {
#pragma unroll
        for (int k = 0; k < 8; ++k) {
            if (k & (1 << (BC - 5))) {
                a[k].x = __shfl_xor_sync(FULL, a[k].x, 1 << BT);
                a[k].y = __shfl_xor_sync(FULL, a[k].y, 1 << BT);
            }
        }
    } else if constexpr (BC < 5 && BT >= 5) {
        const bool cset = (lane >> BC) & 1;
#pragma unroll
        for (int k0 = 0; k0 < 8; ++k0) {
            if (!(k0 & (1 << (BT - 5)))) {
                const int k1 = k0 | (1 << (BT - 5));
                float2 A = a[k0], B = a[k1];
                a[k0] = cset ? B : A;
                a[k1] = cset ? A : B;
            }
        }
    } else {
        const bool cset = (lane >> BC) & 1;
#pragma unroll
        for (int k = 0; k < 8; ++k) {
            float px = __shfl_xor_sync(FULL, a[k].x, 1 << BT);
            float py = __shfl_xor_sync(FULL, a[k].y, 1 << BT);
            if (cset) { a[k].x = px; a[k].y = py; }
        }
    }
}

// Swap register bit R (0..2) with lane bit Q (0..4): element at (k_R=a, l_Q=b)
// moves to (k_R=b, l_Q=a). Only a!=b elements travel: 8 SHFL total.
template<int R, int Q>
__device__ __forceinline__ void swap_bits(float2 (&a)[8], int lane) {
    const bool lq = (lane >> Q) & 1;
#pragma unroll
    for (int k0 = 0; k0 < 8; ++k0) {
        if (k0 & (1 << R)) continue;
        const int k1 = k0 | (1 << R);
        float sx = lq ? a[k0].x : a[k1].x;
        float sy = lq ? a[k0].y : a[k1].y;
        float rx = __shfl_xor_sync(FULL, sx, 1 << Q);
        float ry = __shfl_xor_sync(FULL, sy, 1 << Q);
        a[k0].x = lq ? rx : a[k0].x;
        a[k0].y = lq ? ry : a[k0].y;
        a[k1].x = lq ? a[k1].x : rx;
        a[k1].y = lq ? a[k1].y : ry;
    }
}

// ---------------------------------------------------------------------------
// Fused kernel: block b = bs row b. 8 warps = 8 heads.
// ---------------------------------------------------------------------------
template<bool D2>
__global__ void __launch_bounds__(256)
fused_kernel(const float* __restrict__ x,
             const float* __restrict__ params_rx,
             const float* __restrict__ params_rz,
             const float* __restrict__ Wc,
             float* __restrict__ out,
             int depth)
{
    __shared__ float cRx[64], sRx[64], cRz[64], sRz[64];
    __shared__ float qs[64];

    const int tid = threadIdx.x;
    const int dp8 = depth * 8;
    if (tid < dp8) {
        float s_, c_;
        sincosf(params_rx[tid] * 0.5f, &s_, &c_);
        sRx[tid] = s_; cRx[tid] = c_;
    } else if (tid < 2 * dp8) {
        const int i = tid - dp8;
        float s_, c_;
        sincosf(params_rz[i] * 0.5f, &s_, &c_);
        sRz[i] = s_; cRz[i] = c_;
    }
    __syncthreads();

    const int lane = tid & 31;
    const int h    = tid >> 5;
    const int bs   = blockIdx.x;

    // ---- Fused encoding + layer-0 RX: phi_w = x_w + prx[0,w] ----
    float myc = 0.f, mys = 0.f;
    if (lane < 8) {
        const float ang = x[bs * 64 + h * 8 + lane] + params_rx[lane];
        __sincosf(ang * 0.5f, &mys, &myc);
    }

    float uc[8], us[8];
#pragma unroll
    for (int w = 0; w < 8; ++w) {
        uc[w] = __shfl_sync(FULL, myc, w);
        us[w] = __shfl_sync(FULL, mys, w);
    }

    // Per-wire single-qubit vectors after layer-0 RZ.
    float2 u0[8], u1[8];
#pragma unroll
    for (int w = 0; w < 8; ++w) {
        const float cz = cRz[w], sz = sRz[w];
        u0[w] = make_float2( cz * uc[w], -sz * uc[w]);
        u1[w] = make_float2( sz * us[w], -cz * us[w]);
    }

    // ---- Direct construction of Ring0( product state ) ----
    const int f0 = lane & 1, f1 = (lane >> 1) & 1, f2 = (lane >> 2) & 1;
    const int f3 = (lane >> 3) & 1, f4 = (lane >> 4) & 1;

    const int b4 = f3 ^ f4, b5 = f2 ^ f3, b6 = f1 ^ f2, b7 = f0 ^ f1;
    float2 L = cmul(cmul(b4 ? u1[4] : u0[4], b5 ? u1[5] : u0[5]),
                    cmul(b6 ? u1[6] : u0[6], b7 ? u1[7] : u0[7]));

    float2 A[4], LB[4];
#pragma unroll
    for (int j = 0; j < 4; ++j) {
        const int jk2 = j >> 1, jk1 = j & 1;
        A[j] = cmul((jk2 ^ f0) ? u1[0] : u0[0],
                    (jk1 ^ jk2 ^ f0) ? u1[1] : u0[1]);
    }
#pragma unroll
    for (int j = 0; j < 4; ++j) {
        const int jk1 = j >> 1, jk0 = j & 1;
        float2 B = cmul((jk0 ^ jk1) ? u1[2] : u0[2],
                        (f4 ^ jk0) ? u1[3] : u0[3]);
        LB[j] = cmul(L, B);
    }

    float2 a[8];
#pragma unroll
    for (int k = 0; k < 8; ++k)
        a[k] = cmul(A[(k >> 1) & 3], LB[k & 3]);

    float z0, z1, z2, z3, z4, z5, z6, z7;

    if constexpr (D2) {
        // ---- Last layer (depth==2): RX only, via swap-to-register bits ----
        const int base = 8;
        rx_reg<2>(a, cRx[base + 0], sRx[base + 0]);   // wire0 on k2
        rx_reg<1>(a, cRx[base + 1], sRx[base + 1]);   // wire1 on k1
        rx_reg<0>(a, cRx[base + 2], sRx[base + 2]);   // wire2 on k0
        swap_bits<2, 4>(a, lane);                     // k2 <-> f4 (wire3 in)
        rx_reg<2>(a, cRx[base + 3], sRx[base + 3]);   // wire3
        swap_bits<1, 3>(a, lane);                     // k1 <-> f3 (wire4 in)
        rx_reg<1>(a, cRx[base + 4], sRx[base + 4]);   // wire4
        swap_bits<0, 2>(a, lane);                     // k0 <-> f2 (wire5 in)
        rx_reg<0>(a, cRx[base + 5], sRx[base + 5]);   // wire5
        swap_bits<2, 1>(a, lane);                     // k2 <-> f1 (wire6 in)
        rx_reg<2>(a, cRx[base + 6], sRx[base + 6]);   // wire6
        swap_bits<1, 0>(a, lane);                     // k1 <-> f0 (wire7 in)
        rx_reg<1>(a, cRx[base + 7], sRx[base + 7]);   // wire7

        // Final layout: f4=w0 f3=w1 f2=w2 f1=w3 f0=w4 ; k0=w5 k1=w7 k2=w6
        float p[8];
#pragma unroll
        for (int k = 0; k < 8; ++k)
            p[k] = fmaf(a[k].x, a[k].x, a[k].y * a[k].y);

        // k-space parities: pairs over k0
        const float v0 = p[0] - p[1], v1 = p[2] - p[3];
        const float v2 = p[4] - p[5], v3 = p[6] - p[7];
        const float u0s = p[0] + p[1], u1s = p[2] + p[3];
        const float u2s = p[4] + p[5], u3s = p[6] + p[7];

        const float P0 = (u0s + u1s) + (u2s + u3s);           // parity {}
        const float P1 = (v0 + v1) + (v2 + v3);               // parity {k0}
        const float P2 = (v0 + v1) - (v2 + v3);               // parity {k0,k2}
        const float P3 = (v0 - v1) - (v2 - v3);               // parity {k0,k1,k2}

        // Lane-sign chains (wires 0..4 on f4..f0):
        const int g1 = f4 ^ f3;
        const int g2 = g1 ^ f2;
        const int g3 = g2 ^ f1;
        const int g4 = g3 ^ f0;
        const int gz0 = g4 ^ f4;   // f3^f2^f1^f0

        // Folded observables: Z0 -> Z(w1..w7) ; Zw -> Z(w0..ww)
        z0 = gz0 ? -P3 : P3;
        z1 = g1 ? -P0 : P0;
        z2 = g2 ? -P0 : P0;
        z3 = g3 ? -P0 : P0;
        z4 = g4 ? -P0 : P0;
        z5 = g4 ? -P1 : P1;
        z6 = g4 ? -P2 : P2;
        z7 = g4 ? -P3 : P3;
    } else {
        // ---- Generic path (depth != 2): original verified code ----
        for (int l = 1; l < depth - 1; ++l) {
            const int base = l * 8;
#define APPLY_LW(W) do {                                             \
                rx_wire<(W)>(a, cRx[base + (W)], sRx[base + (W)]);   \
                rz_wire<(W)>(a, lane, cRz[base + (W)], sRz[base + (W)]); \
            } while (0)
            APPLY_LW(0); APPLY_LW(1); APPLY_LW(2); APPLY_LW(3);
            APPLY_LW(4); APPLY_LW(5); APPLY_LW(6); APPLY_LW(7);
#undef APPLY_LW
            cnot<7, 6>(a, lane);
            cnot<6, 5>(a, lane);
            cnot<5, 4>(a, lane);
            cnot<4, 3>(a, lane);
            cnot<3, 2>(a, lane);
            cnot<2, 1>(a, lane);
            cnot<1, 0>(a, lane);
            cnot<0, 7>(a, lane);
        }

        if (depth >= 2) {
            const int base = (depth - 1) * 8;
            rx_wire<0>(a, cRx[base + 0], sRx[base + 0]);
            rx_wire<1>(a, cRx[base + 1], sRx[base + 1]);
            rx_wire<2>(a, cRx[base + 2], sRx[base + 2]);
            rx_wire<3>(a, cRx[base + 3], sRx[base + 3]);
            rx_wire<4>(a, cRx[base + 4], sRx[base + 4]);
            rx_wire<5>(a, cRx[base + 5], sRx[base + 5]);
            rx_wire<6>(a, cRx[base + 6], sRx[base + 6]);
            rx_wire<7>(a, cRx[base + 7], sRx[base + 7]);

            float p[8];
#pragma unroll
            for (int k = 0; k < 8; ++k)
                p[k] = fmaf(a[k].x, a[k].x, a[k].y * a[k].y);

            float sK = 0.f, s01 = 0.f, s12 = 0.f;
#pragma unroll
            for (int k = 0; k < 8; ++k) {
                const int pk  = __popc(k) & 1;
                const int p01 = __popc(k & 3) & 1;
                const int p12 = __popc(k >> 1) & 1;
                sK  += pk  ? -p[k] : p[k];
                s01 += p01 ? -p[k] : p[k];
                s12 += p12 ? -p[k] : p[k];
            }

            const int m3 = f4;
            const int m4 = m3 ^ f3;
            const int m5 = m4 ^ f2;
            const int m6 = m5 ^ f1;
            const int m7 = m6 ^ f0;

            z0 = m7 ? -s01 : s01;
            z1 = s12;
            z2 = sK;
            z3 = m3 ? -sK : sK;
            z4 = m4 ? -sK : sK;
            z5 = m5 ? -sK : sK;
            z6 = m6 ? -sK : sK;
            z7 = m7 ? -sK : sK;
        } else {
            float p[8];
#pragma unroll
            for (int k = 0; k < 8; ++k)
                p[k] = fmaf(a[k].x, a[k].x, a[k].y * a[k].y);
            float sA = 0.f, s0 = 0.f, s1 = 0.f, s2 = 0.f;
#pragma unroll
            for (int k = 0; k < 8; ++k) {
                sA += p[k];
                s0 += ((k >> 2) & 1) ? -p[k] : p[k];
                s1 += ((k >> 1) & 1) ? -p[k] : p[k];
                s2 += ((k     ) & 1) ? -p[k] : p[k];
            }
            z0 = s0; z1 = s1; z2 = s2;
            z3 = f4 ? -sA : sA;
            z4 = f3 ? -sA : sA;
            z5 = f2 ? -sA : sA;
            z6 = f1 ? -sA : sA;
            z7 = f0 ? -sA : sA;
        }
    }

    // ---- Reduce-scatter: 8 values over 32 lanes in 9 shuffles ----
    float K0, K1, K2, K3;
    {
        const bool b = lane & 1;
        float s0 = b ? z0 : z4;
        float s1 = b ? z1 : z5;
        float s2 = b ? z2 : z6;
        float s3 = b ? z3 : z7;
        K0 = (b ? z4 : z0) + __shfl_xor_sync(FULL, s0, 1);
        K1 = (b ? z5 : z1) + __shfl_xor_sync(FULL, s1, 1);
        K2 = (b ? z6 : z2) + __shfl_xor_sync(FULL, s2, 1);
        K3 = (b ? z7 : z3) + __shfl_xor_sync(FULL, s3, 1);
    }
    float J0, J1;
    {
        const bool b = lane & 2;
        float s0 = b ? K0 : K2;
        float s1 = b ? K1 : K3;
        J0 = (b ? K2 : K0) + __shfl_xor_sync(FULL, s0, 2);
        J1 = (b ? K3 : K1) + __shfl_xor_sync(FULL, s1, 2);
    }
    float T;
    {
        const bool b = lane & 4;
        float s0 = b ? J0 : J1;
        T = (b ? J1 : J0) + __shfl_xor_sync(FULL, s0, 4);
    }
    T += __shfl_xor_sync(FULL, T, 8);
    T += __shfl_xor_sync(FULL, T, 16);

    if (lane < 8) {
        const int v = ((lane & 1) << 2) | (lane & 2) | ((lane >> 2) & 1);
        qs[h * 8 + v] = T;
    }
    __syncthreads();

    // ---- Combine: warp h computes out[bs, h*8 .. h*8+8) ----
    const int eo = lane & 7;
    const int p_ = lane >> 3;
    const int e  = h * 8 + eo;

    const float4* q4 = reinterpret_cast<const float4*>(qs + p_ * 16);
    const float4* w4 = reinterpret_cast<const float4*>(Wc + e * 64 + p_ * 16);

    float acc = 0.f;
#pragma unroll
    for (int i = 0; i < 4; ++i) {
        const float4 qv = q4[i];
        const float4 wv = w4[i];
        acc = fmaf(qv.x, wv.x, acc);
        acc = fmaf(qv.y, wv.y, acc);
        acc = fmaf(qv.z, wv.z, acc);
        acc = fmaf(qv.w, wv.w, acc);
    }
    acc += __shfl_xor_sync(FULL, acc, 8);
    acc += __shfl_xor_sync(FULL, acc, 16);

    if (p_ == 0)
        out[bs * 64 + e] = acc;
}

// ---------------------------------------------------------------------------
extern "C" void kernel_launch(void* const* d_in, const int* in_sizes, int n_in,
                              void* d_out, int out_size)
{
    const float* x    = (const float*)d_in[0];      // [B,S,64]
    const float* prx  = (const float*)d_in[1];      // [depth,8]
    const float* prz  = (const float*)d_in[2];      // [depth,8]
    const float* W    = (const float*)d_in[3];      // [64,64]
    float* out        = (float*)d_out;              // [B,S,64]

    const int BS    = in_sizes[0] / 64;             // 2048
    const int depth = in_sizes[1] / 8;              // 2

    if (depth == 2)
        fused_kernel<true><<<BS, 256>>>(x, prx, prz, W, out, depth);
    else
        fused_kernel<false><<<BS, 256>>>(x, prx, prz, W, out, depth);
}

// round 6
// speedup vs baseline: 1.4541x; 1.4541x over previous
#include <cuda_runtime.h>
#include <cuda_bf16.h>
#include <cstdint>

#define FULL 0xFFFFFFFFu

__device__ __forceinline__ float2 cmul(float2 a, float2 b) {
    return make_float2(fmaf(a.x, b.x, -a.y * b.y),
                       fmaf(a.x, b.y,  a.y * b.x));
}

// ---------------------------------------------------------------------------
// Layout: one warp per token. Lane l holds amplitudes flat=(k<<5)|l, k=0..7.
// Wire w <-> flat bit (7-w). flat bits 0..4 = lane bits (wires 7..3),
// flat bits 5..7 = k bits k0,k1,k2 (wires 2,1,0).
// ---------------------------------------------------------------------------

template<int RB>
__device__ __forceinline__ void rx_reg(float2 (&a)[8], float c, float s) {
#pragma unroll
    for (int k0 = 0; k0 < 8; ++k0) {
        if (k0 & (1 << RB)) continue;
        const int k1 = k0 | (1 << RB);
        float2 A = a[k0], B = a[k1];
        a[k0].x = fmaf(c, A.x,  s * B.y);
        a[k0].y = fmaf(c, A.y, -s * B.x);
        a[k1].x = fmaf(c, B.x,  s * A.y);
        a[k1].y = fmaf(c, B.y, -s * A.x);
    }
}

template<int B>
__device__ __forceinline__ void rx_lane(float2 (&a)[8], float c, float s) {
#pragma unroll
    for (int k = 0; k < 8; ++k) {
        float px = __shfl_xor_sync(FULL, a[k].x, 1 << B);
        float py = __shfl_xor_sync(FULL, a[k].y, 1 << B);
        float nx = fmaf(c, a[k].x,  s * py);
        float ny = fmaf(c, a[k].y, -s * px);
        a[k].x = nx; a[k].y = ny;
    }
}

template<int W>
__device__ __forceinline__ void rx_wire(float2 (&a)[8], float c, float s) {
    constexpr int B = 7 - W;
    if constexpr (B >= 5) rx_reg<B - 5>(a, c, s);
    else                  rx_lane<B>(a, c, s);
}

template<int W>
__device__ __forceinline__ void rz_wire(float2 (&a)[8], int lane, float c, float s) {
    constexpr int B = 7 - W;
#pragma unroll
    for (int k = 0; k < 8; ++k) {
        int bit;
        if constexpr (B >= 5) bit = (k >> (B - 5)) & 1;
        else                  bit = (lane >> B) & 1;
        float t = bit ? s : -s;
        float nx = fmaf(a[k].x, c, -a[k].y * t);
        float ny = fmaf(a[k].y, c,  a[k].x * t);
        a[k].x = nx; a[k].y = ny;
    }
}

template<int BC, int BT>
__device__ __forceinline__ void cnot(float2 (&a)[8], int lane) {
    if constexpr (BC >= 5 && BT >= 5) {
#pragma unroll
        for (int k = 0; k < 8; ++k) {
            if ((k & (1 << (BC - 5))) && !(k & (1 << (BT - 5)))) {
                const int k2 = k | (1 << (BT - 5));
                float2 t = a[k]; a[k] = a[k2]; a[k2] = t;
            }
        }
    } else if constexpr (BC >= 5 && BT < 5) {
#pragma unroll
        for (int k = 0; k < 8; ++k) {
            if (k & (1 << (BC - 5))) {
                a[k].x = __shfl_xor_sync(FULL, a[k].x, 1 << BT);
                a[k].y = __shfl_xor_sync(FULL, a[k].y, 1 << BT);
            }
        }
    } else if constexpr (BC < 5 && BT >= 5) {
        const bool cset = (lane >> BC) & 1;
#pragma unroll
        for (int k0 = 0; k0 < 8; ++k0) {
            if (!(k0 & (1 << (BT - 5)))) {
                const int k1 = k0 | (1 << (BT - 5));
                float2 A = a[k0], B = a[k1];
                a[k0] = cset ? B : A;
                a[k1] = cset ? A : B;
            }
        }
    } else {
        const bool cset = (lane >> BC) & 1;
#pragma unroll
        for (int k = 0; k < 8; ++k) {
            float px = __shfl_xor_sync(FULL, a[k].x, 1 << BT);
            float py = __shfl_xor_sync(FULL, a[k].y, 1 << BT);
            if (cset) { a[k].x = px; a[k].y = py; }
        }
    }
}

// ---------------------------------------------------------------------------
// Fused kernel: block b = bs row b. 8 warps = 8 heads.
// ---------------------------------------------------------------------------
template<bool D2>
__global__ void __launch_bounds__(256, 7)
fused_kernel(const float* __restrict__ x,
             const float* __restrict__ params_rx,
             const float* __restrict__ params_rz,
             const float* __restrict__ Wc,
             float* __restrict__ out,
             int depth)
{
    __shared__ float cRx[64], sRx[64], cRz[64], sRz[64];
    __shared__ float qs[64];

    const int tid = threadIdx.x;
    const int dp8 = depth * 8;
    if (tid < dp8) {
        float s_, c_;
        sincosf(params_rx[tid] * 0.5f, &s_, &c_);
        sRx[tid] = s_; cRx[tid] = c_;
    } else if (tid < 2 * dp8) {
        const int i = tid - dp8;
        float s_, c_;
        sincosf(params_rz[i] * 0.5f, &s_, &c_);
        sRz[i] = s_; cRz[i] = c_;
    }
    __syncthreads();

    const int lane = tid & 31;
    const int h    = tid >> 5;
    const int bs   = blockIdx.x;

    // ---- Fused encoding + layer-0 RX: phi_w = x_w + prx[0,w] ----
    float myc = 0.f, mys = 0.f;
    if (lane < 8) {
        const float ang = x[bs * 64 + h * 8 + lane] + params_rx[lane];
        __sincosf(ang * 0.5f, &mys, &myc);
    }

    float uc[8], us[8];
#pragma unroll
    for (int w = 0; w < 8; ++w) {
        uc[w] = __shfl_sync(FULL, myc, w);
        us[w] = __shfl_sync(FULL, mys, w);
    }

    // Per-wire single-qubit vectors after layer-0 RZ.
    float2 u0[8], u1[8];
#pragma unroll
    for (int w = 0; w < 8; ++w) {
        const float cz = cRz[w], sz = sRz[w];
        u0[w] = make_float2( cz * uc[w], -sz * uc[w]);
        u1[w] = make_float2( sz * us[w], -cz * us[w]);
    }

    // ---- Direct construction of Ring0( product state ) ----
    const int f0 = lane & 1, f1 = (lane >> 1) & 1, f2 = (lane >> 2) & 1;
    const int f3 = (lane >> 3) & 1, f4 = (lane >> 4) & 1;

    const int b4 = f3 ^ f4, b5 = f2 ^ f3, b6 = f1 ^ f2, b7 = f0 ^ f1;
    float2 L = cmul(cmul(b4 ? u1[4] : u0[4], b5 ? u1[5] : u0[5]),
                    cmul(b6 ? u1[6] : u0[6], b7 ? u1[7] : u0[7]));

    float2 A[4], LB[4];
#pragma unroll
    for (int j = 0; j < 4; ++j) {
        const int jk2 = j >> 1, jk1 = j & 1;
        A[j] = cmul((jk2 ^ f0) ? u1[0] : u0[0],
                    (jk1 ^ jk2 ^ f0) ? u1[1] : u0[1]);
    }
#pragma unroll
    for (int j = 0; j < 4; ++j) {
        const int jk1 = j >> 1, jk0 = j & 1;
        float2 B = cmul((jk0 ^ jk1) ? u1[2] : u0[2],
                        (f4 ^ jk0) ? u1[3] : u0[3]);
        LB[j] = cmul(L, B);
    }

    float2 a[8];
#pragma unroll
    for (int k = 0; k < 8; ++k)
        a[k] = cmul(A[(k >> 1) & 3], LB[k & 3]);

    // ---- Middle layers (only when depth > 2) ----
    if constexpr (!D2) {
        for (int l = 1; l < depth - 1; ++l) {
            const int base = l * 8;
#define APPLY_LW(W) do {                                             \
                rx_wire<(W)>(a, cRx[base + (W)], sRx[base + (W)]);   \
                rz_wire<(W)>(a, lane, cRz[base + (W)], sRz[base + (W)]); \
            } while (0)
            APPLY_LW(0); APPLY_LW(1); APPLY_LW(2); APPLY_LW(3);
            APPLY_LW(4); APPLY_LW(5); APPLY_LW(6); APPLY_LW(7);
#undef APPLY_LW
            cnot<7, 6>(a, lane);
            cnot<6, 5>(a, lane);
            cnot<5, 4>(a, lane);
            cnot<4, 3>(a, lane);
            cnot<3, 2>(a, lane);
            cnot<2, 1>(a, lane);
            cnot<1, 0>(a, lane);
            cnot<0, 7>(a, lane);
        }
    }

    float z0, z1, z2, z3, z4, z5, z6, z7;

    if (D2 || depth >= 2) {
        // ---- Last layer: RX only (RZ dropped, ring folded into observables) ----
        const int base = (depth - 1) * 8;
        rx_wire<0>(a, cRx[base + 0], sRx[base + 0]);
        rx_wire<1>(a, cRx[base + 1], sRx[base + 1]);
        rx_wire<2>(a, cRx[base + 2], sRx[base + 2]);
        rx_wire<3>(a, cRx[base + 3], sRx[base + 3]);
        rx_wire<4>(a, cRx[base + 4], sRx[base + 4]);
        rx_wire<5>(a, cRx[base + 5], sRx[base + 5]);
        rx_wire<6>(a, cRx[base + 6], sRx[base + 6]);
        rx_wire<7>(a, cRx[base + 7], sRx[base + 7]);

        float p[8];
#pragma unroll
        for (int k = 0; k < 8; ++k)
            p[k] = fmaf(a[k].x, a[k].x, a[k].y * a[k].y);

        // Folded observables: Z0 -> Z1..Z7 ; Zw -> Z0..Zw (w>=1)
        float sK = 0.f, s01 = 0.f, s12 = 0.f;
#pragma unroll
        for (int k = 0; k < 8; ++k) {
            const int pk  = __popc(k) & 1;
            const int p01 = __popc(k & 3) & 1;
            const int p12 = __popc(k >> 1) & 1;
            sK  += pk  ? -p[k] : p[k];
            s01 += p01 ? -p[k] : p[k];
            s12 += p12 ? -p[k] : p[k];
        }

        const int m3 = f4;
        const int m4 = m3 ^ f3;
        const int m5 = m4 ^ f2;
        const int m6 = m5 ^ f1;
        const int m7 = m6 ^ f0;

        z0 = m7 ? -s01 : s01;
        z1 = s12;
        z2 = sK;
        z3 = m3 ? -sK : sK;
        z4 = m4 ? -sK : sK;
        z5 = m5 ? -sK : sK;
        z6 = m6 ? -sK : sK;
        z7 = m7 ? -sK : sK;
    } else {
        float p[8];
#pragma unroll
        for (int k = 0; k < 8; ++k)
            p[k] = fmaf(a[k].x, a[k].x, a[k].y * a[k].y);
        float sA = 0.f, s0 = 0.f, s1 = 0.f, s2 = 0.f;
#pragma unroll
        for (int k = 0; k < 8; ++k) {
            sA += p[k];
            s0 += ((k >> 2) & 1) ? -p[k] : p[k];
            s1 += ((k >> 1) & 1) ? -p[k] : p[k];
            s2 += ((k     ) & 1) ? -p[k] : p[k];
        }
        z0 = s0; z1 = s1; z2 = s2;
        z3 = f4 ? -sA : sA;
        z4 = f3 ? -sA : sA;
        z5 = f2 ? -sA : sA;
        z6 = f1 ? -sA : sA;
        z7 = f0 ? -sA : sA;
    }

    // ---- Reduce-scatter: 8 values over 32 lanes in 9 shuffles ----
    float K0, K1, K2, K3;
    {
        const bool b = lane & 1;
        float s0 = b ? z0 : z4;
        float s1 = b ? z1 : z5;
        float s2 = b ? z2 : z6;
        float s3 = b ? z3 : z7;
        K0 = (b ? z4 : z0) + __shfl_xor_sync(FULL, s0, 1);
        K1 = (b ? z5 : z1) + __shfl_xor_sync(FULL, s1, 1);
        K2 = (b ? z6 : z2) + __shfl_xor_sync(FULL, s2, 1);
        K3 = (b ? z7 : z3) + __shfl_xor_sync(FULL, s3, 1);
    }
    float J0, J1;
    {
        const bool b = lane & 2;
        float s0 = b ? K0 : K2;
        float s1 = b ? K1 : K3;
        J0 = (b ? K2 : K0) + __shfl_xor_sync(FULL, s0, 2);
        J1 = (b ? K3 : K1) + __shfl_xor_sync(FULL, s1, 2);
    }
    float T;
    {
        const bool b = lane & 4;
        float s0 = b ? J0 : J1;
        T = (b ? J1 : J0) + __shfl_xor_sync(FULL, s0, 4);
    }
    T += __shfl_xor_sync(FULL, T, 8);
    T += __shfl_xor_sync(FULL, T, 16);

    if (lane < 8) {
        const int v = ((lane & 1) << 2) | (lane & 2) | ((lane >> 2) & 1);
        qs[h * 8 + v] = T;
    }
    __syncthreads();

    // ---- Combine (coalesced): warp h computes out[bs, 8h .. 8h+8) ----
    // W rows for this warp are one contiguous 2KB block. Lane l, iter i reads
    // flat float4 chunk c = i*32 + l:  e_local = c>>4 = 2i + (l>>4),
    // j-quad = (c & 15). Reduce each acc over the 16-lane half.
    const float4* W4 = reinterpret_cast<const float4*>(Wc + h * 512);
    const float4* q4 = reinterpret_cast<const float4*>(qs);

    float acc[4];
#pragma unroll
    for (int i = 0; i < 4; ++i) {
        const int c = i * 32 + lane;
        const float4 wv = W4[c];
        const float4 qv = q4[c & 15];
        acc[i] = fmaf(qv.x, wv.x,
                 fmaf(qv.y, wv.y,
                 fmaf(qv.z, wv.z, qv.w * wv.w)));
    }
#pragma unroll
    for (int off = 1; off <= 8; off <<= 1) {
#pragma unroll
        for (int i = 0; i < 4; ++i)
            acc[i] += __shfl_xor_sync(FULL, acc[i], off);
    }

    if ((lane & 15) == 0) {
        float* o = out + bs * 64 + h * 8 + (lane >> 4);  // e = 2i + (lane>>4)
        o[0] = acc[0];
        o[2] = acc[1];
        o[4] = acc[2];
        o[6] = acc[3];
    }
}

// ---------------------------------------------------------------------------
extern "C" void kernel_launch(void* const* d_in, const int* in_sizes, int n_in,
                              void* d_out, int out_size)
{
    const float* x    = (const float*)d_in[0];      // [B,S,64]
    const float* prx  = (const float*)d_in[1];      // [depth,8]
    const float* prz  = (const float*)d_in[2];      // [depth,8]
    const float* W    = (const float*)d_in[3];      // [64,64]
    float* out        = (float*)d_out;              // [B,S,64]

    const int BS    = in_sizes[0] / 64;             // 2048
    const int depth = in_sizes[1] / 8;              // 2

    if (depth == 2)
        fused_kernel<true><<<BS, 256>>>(x, prx, prz, W, out, depth);
    else
        fused_kernel<false><<<BS, 256>>>(x, prx, prz, W, out, depth);
}

// round 7
// speedup vs baseline: 1.6250x; 1.1175x over previous
#include <cuda_runtime.h>
#include <cuda_bf16.h>
#include <cstdint>

#define FULL 0xFFFFFFFFu
typedef unsigned long long ull;

__device__ __forceinline__ float2 cmul(float2 a, float2 b) {
    return make_float2(fmaf(a.x, b.x, -a.y * b.y),
                       fmaf(a.x, b.y,  a.y * b.x));
}

// ---- packed f32x2 helpers ----
__device__ __forceinline__ ull pack2(float lo, float hi) {
    ull r; asm("mov.b64 %0, {%1, %2};" : "=l"(r) : "f"(lo), "f"(hi)); return r;
}
__device__ __forceinline__ void unpack2(ull v, float& lo, float& hi) {
    asm("mov.b64 {%0, %1}, %2;" : "=f"(lo), "=f"(hi) : "l"(v));
}
__device__ __forceinline__ ull fma2(ull a, ull b, ull c) {   // a*b + c
    ull r; asm("fma.rn.f32x2 %0, %1, %2, %3;" : "=l"(r) : "l"(a), "l"(b), "l"(c)); return r;
}
__device__ __forceinline__ ull mul2(ull a, ull b) {
    ull r; asm("mul.rn.f32x2 %0, %1, %2;" : "=l"(r) : "l"(a), "l"(b)); return r;
}
__device__ __forceinline__ ull swap2(ull v) {
    float lo, hi; unpack2(v, lo, hi); return pack2(hi, lo);
}
__device__ __forceinline__ ull shfl2(ull v, int m) {
    return __shfl_xor_sync(FULL, v, m);
}

// ---------------------------------------------------------------------------
// Layout: one warp per token. Lane l holds amplitudes flat=(k<<5)|l, k=0..7.
// Wire w <-> flat bit (7-w). flat bits 0..4 = lane bits (wires 7..3),
// flat bits 5..7 = k bits k0,k1,k2 (wires 2,1,0).
// ---------------------------------------------------------------------------

template<int RB>
__device__ __forceinline__ void rx_reg(float2 (&a)[8], float c, float s) {
#pragma unroll
    for (int k0 = 0; k0 < 8; ++k0) {
        if (k0 & (1 << RB)) continue;
        const int k1 = k0 | (1 << RB);
        float2 A = a[k0], B = a[k1];
        a[k0].x = fmaf(c, A.x,  s * B.y);
        a[k0].y = fmaf(c, A.y, -s * B.x);
        a[k1].x = fmaf(c, B.x,  s * A.y);
        a[k1].y = fmaf(c, B.y, -s * A.x);
    }
}

template<int B>
__device__ __forceinline__ void rx_lane(float2 (&a)[8], float c, float s) {
#pragma unroll
    for (int k = 0; k < 8; ++k) {
        float px = __shfl_xor_sync(FULL, a[k].x, 1 << B);
        float py = __shfl_xor_sync(FULL, a[k].y, 1 << B);
        float nx = fmaf(c, a[k].x,  s * py);
        float ny = fmaf(c, a[k].y, -s * px);
        a[k].x = nx; a[k].y = ny;
    }
}

template<int W>
__device__ __forceinline__ void rx_wire(float2 (&a)[8], float c, float s) {
    constexpr int B = 7 - W;
    if constexpr (B >= 5) rx_reg<B - 5>(a, c, s);
    else                  rx_lane<B>(a, c, s);
}

template<int W>
__device__ __forceinline__ void rz_wire(float2 (&a)[8], int lane, float c, float s) {
    constexpr int B = 7 - W;
#pragma unroll
    for (int k = 0; k < 8; ++k) {
        int bit;
        if constexpr (B >= 5) bit = (k >> (B - 5)) & 1;
        else                  bit = (lane >> B) & 1;
        float t = bit ? s : -s;
        float nx = fmaf(a[k].x, c, -a[k].y * t);
        float ny = fmaf(a[k].y, c,  a[k].x * t);
        a[k].x = nx; a[k].y = ny;
    }
}

template<int BC, int BT>
__device__ __forceinline__ void cnot(float2 (&a)[8], int lane) {
    if constexpr (BC >= 5 && BT >= 5) {
#pragma unroll
        for (int k = 0; k < 8; ++k) {
            if ((k & (1 << (BC - 5))) && !(k & (1 << (BT - 5)))) {
                const int k2 = k | (1 << (BT - 5));
                float2 t = a[k]; a[k] = a[k2]; a[k2] = t;
            }
        }
    } else if constexpr (BC >= 5 && BT < 5) {
#pragma unroll
        for (int k = 0; k < 8; ++k) {
            if (k & (1 << (BC - 5))) {
                a[k].x = __shfl_xor_sync(FULL, a[k].x, 1 << BT);
                a[k].y = __shfl_xor_sync(FULL, a[k].y, 1 << BT);
            }
        }
    } else if constexpr (BC < 5 && BT >= 5) {
        const bool cset = (lane >> BC) & 1;
#pragma unroll
        for (int k0 = 0; k0 < 8; ++k0) {
            if (!(k0 & (1 << (BT - 5)))) {
                const int k1 = k0 | (1 << (BT - 5));
                float2 A = a[k0], B = a[k1];
                a[k0] = cset ? B : A;
                a[k1] = cset ? A : B;
            }
        }
    } else {
        const bool cset = (lane >> BC) & 1;
#pragma unroll
        for (int k = 0; k < 8; ++k) {
            float px = __shfl_xor_sync(FULL, a[k].x, 1 << BT);
            float py = __shfl_xor_sync(FULL, a[k].y, 1 << BT);
            if (cset) { a[k].x = px; a[k].y = py; }
        }
    }
}

// ---------------------------------------------------------------------------
// Fused kernel: block b = bs row b. 8 warps = 8 heads.
// ---------------------------------------------------------------------------
template<bool D2>
__global__ void __launch_bounds__(256, 7)
fused_kernel(const float* __restrict__ x,
             const float* __restrict__ params_rx,
             const float* __restrict__ params_rz,
             const float* __restrict__ Wc,
             float* __restrict__ out,
             int depth)
{
    __shared__ float cRx[64], sRx[64], cRz[64], sRz[64];
    __shared__ float qs[64];

    const int tid = threadIdx.x;
    const int dp8 = depth * 8;
    if (tid < dp8) {
        float s_, c_;
        sincosf(params_rx[tid] * 0.5f, &s_, &c_);
        sRx[tid] = s_; cRx[tid] = c_;
    } else if (tid < 2 * dp8) {
        const int i = tid - dp8;
        float s_, c_;
        sincosf(params_rz[i] * 0.5f, &s_, &c_);
        sRz[i] = s_; cRz[i] = c_;
    }
    __syncthreads();

    const int lane = tid & 31;
    const int h    = tid >> 5;
    const int bs   = blockIdx.x;

    // ---- Fused encoding + layer-0 RX: phi_w = x_w + prx[0,w] ----
    float myc = 0.f, mys = 0.f;
    if (lane < 8) {
        const float ang = x[bs * 64 + h * 8 + lane] + params_rx[lane];
        __sincosf(ang * 0.5f, &mys, &myc);
    }

    float uc[8], us[8];
#pragma unroll
    for (int w = 0; w < 8; ++w) {
        uc[w] = __shfl_sync(FULL, myc, w);
        us[w] = __shfl_sync(FULL, mys, w);
    }

    // Per-wire single-qubit vectors after layer-0 RZ.
    float2 u0[8], u1[8];
#pragma unroll
    for (int w = 0; w < 8; ++w) {
        const float cz = cRz[w], sz = sRz[w];
        u0[w] = make_float2( cz * uc[w], -sz * uc[w]);
        u1[w] = make_float2( sz * us[w], -cz * us[w]);
    }

    // ---- Direct construction of Ring0( product state ) ----
    const int f0 = lane & 1, f1 = (lane >> 1) & 1, f2 = (lane >> 2) & 1;
    const int f3 = (lane >> 3) & 1, f4 = (lane >> 4) & 1;

    const int b4 = f3 ^ f4, b5 = f2 ^ f3, b6 = f1 ^ f2, b7 = f0 ^ f1;
    float2 L = cmul(cmul(b4 ? u1[4] : u0[4], b5 ? u1[5] : u0[5]),
                    cmul(b6 ? u1[6] : u0[6], b7 ? u1[7] : u0[7]));

    float2 A[4], LB[4];
#pragma unroll
    for (int j = 0; j < 4; ++j) {
        const int jk2 = j >> 1, jk1 = j & 1;
        A[j] = cmul((jk2 ^ f0) ? u1[0] : u0[0],
                    (jk1 ^ jk2 ^ f0) ? u1[1] : u0[1]);
    }
#pragma unroll
    for (int j = 0; j < 4; ++j) {
        const int jk1 = j >> 1, jk0 = j & 1;
        float2 B = cmul((jk0 ^ jk1) ? u1[2] : u0[2],
                        (f4 ^ jk0) ? u1[3] : u0[3]);
        LB[j] = cmul(L, B);
    }

    float2 a[8];
#pragma unroll
    for (int k = 0; k < 8; ++k)
        a[k] = cmul(A[(k >> 1) & 3], LB[k & 3]);

    float z0, z1, z2, z3, z4, z5, z6, z7;

    if constexpr (D2) {
        // ---- depth==2: last layer RX only, packed f32x2 (pack along k0) ----
        // X[j] = (a[2j].x, a[2j+1].x), Y[j] = (a[2j].y, a[2j+1].y)
        ull X[4], Y[4];
#pragma unroll
        for (int j = 0; j < 4; ++j) {
            X[j] = pack2(a[2 * j].x, a[2 * j + 1].x);
            Y[j] = pack2(a[2 * j].y, a[2 * j + 1].y);
        }

        const int base = 8;
        // wire0 on k2: partner j ^ 2
        {
            const float c = cRx[base + 0], s = sRx[base + 0];
            const ull c2 = pack2(c, c), sp = pack2(s, s), sn = pack2(-s, -s);
#pragma unroll
            for (int j = 0; j < 2; ++j) {
                const int j2 = j + 2;
                ull nX0 = fma2(sp, Y[j2], mul2(c2, X[j]));
                ull nY0 = fma2(sn, X[j2], mul2(c2, Y[j]));
                ull nX1 = fma2(sp, Y[j],  mul2(c2, X[j2]));
                ull nY1 = fma2(sn, X[j],  mul2(c2, Y[j2]));
                X[j] = nX0; Y[j] = nY0; X[j2] = nX1; Y[j2] = nY1;
            }
        }
        // wire1 on k1: partner j ^ 1
        {
            const float c = cRx[base + 1], s = sRx[base + 1];
            const ull c2 = pack2(c, c), sp = pack2(s, s), sn = pack2(-s, -s);
#pragma unroll
            for (int j = 0; j < 4; j += 2) {
                const int j2 = j + 1;
                ull nX0 = fma2(sp, Y[j2], mul2(c2, X[j]));
                ull nY0 = fma2(sn, X[j2], mul2(c2, Y[j]));
                ull nX1 = fma2(sp, Y[j],  mul2(c2, X[j2]));
                ull nY1 = fma2(sn, X[j],  mul2(c2, Y[j2]));
                X[j] = nX0; Y[j] = nY0; X[j2] = nX1; Y[j2] = nY1;
            }
        }
        // wire2 on k0: within-pack butterfly (component swap)
        {
            const float c = cRx[base + 2], s = sRx[base + 2];
            const ull c2 = pack2(c, c), sp = pack2(s, s), sn = pack2(-s, -s);
#pragma unroll
            for (int j = 0; j < 4; ++j) {
                const ull sX = swap2(X[j]), sY = swap2(Y[j]);
                X[j] = fma2(sp, sY, mul2(c2, X[j]));
                Y[j] = fma2(sn, sX, mul2(c2, Y[j]));
            }
        }
        // wires 3..7 on lane bits 4..0
#pragma unroll
        for (int w = 3; w < 8; ++w) {
            const int m = 1 << (7 - w);
            const float c = cRx[base + w], s = sRx[base + w];
            const ull c2 = pack2(c, c), sp = pack2(s, s), sn = pack2(-s, -s);
#pragma unroll
            for (int j = 0; j < 4; ++j) {
                const ull PX = shfl2(X[j], m);
                const ull PY = shfl2(Y[j], m);
                X[j] = fma2(sp, PY, mul2(c2, X[j]));
                Y[j] = fma2(sn, PX, mul2(c2, Y[j]));
            }
        }

        // ---- probabilities (packed) ----
        float p[8];
#pragma unroll
        for (int j = 0; j < 4; ++j) {
            const ull P = fma2(X[j], X[j], mul2(Y[j], Y[j]));
            unpack2(P, p[2 * j], p[2 * j + 1]);
        }

        // Folded observables: Z0 -> Z1..Z7 ; Zw -> Z0..Zw (w>=1)
        float sK = 0.f, s01 = 0.f, s12 = 0.f;
#pragma unroll
        for (int k = 0; k < 8; ++k) {
            const int pk  = __popc(k) & 1;
            const int p01 = __popc(k & 3) & 1;
            const int p12 = __popc(k >> 1) & 1;
            sK  += pk  ? -p[k] : p[k];
            s01 += p01 ? -p[k] : p[k];
            s12 += p12 ? -p[k] : p[k];
        }

        const int m3 = f4;
        const int m4 = m3 ^ f3;
        const int m5 = m4 ^ f2;
        const int m6 = m5 ^ f1;
        const int m7 = m6 ^ f0;

        z0 = m7 ? -s01 : s01;
        z1 = s12;
        z2 = sK;
        z3 = m3 ? -sK : sK;
        z4 = m4 ? -sK : sK;
        z5 = m5 ? -sK : sK;
        z6 = m6 ? -sK : sK;
        z7 = m7 ? -sK : sK;
    } else {
        // ---- Generic path (depth != 2): original verified code ----
        for (int l = 1; l < depth - 1; ++l) {
            const int base = l * 8;
#define APPLY_LW(W) do {                                             \
                rx_wire<(W)>(a, cRx[base + (W)], sRx[base + (W)]);   \
                rz_wire<(W)>(a, lane, cRz[base + (W)], sRz[base + (W)]); \
            } while (0)
            APPLY_LW(0); APPLY_LW(1); APPLY_LW(2); APPLY_LW(3);
            APPLY_LW(4); APPLY_LW(5); APPLY_LW(6); APPLY_LW(7);
#undef APPLY_LW
            cnot<7, 6>(a, lane);
            cnot<6, 5>(a, lane);
            cnot<5, 4>(a, lane);
            cnot<4, 3>(a, lane);
            cnot<3, 2>(a, lane);
            cnot<2, 1>(a, lane);
            cnot<1, 0>(a, lane);
            cnot<0, 7>(a, lane);
        }

        if (depth >= 2) {
            const int base = (depth - 1) * 8;
            rx_wire<0>(a, cRx[base + 0], sRx[base + 0]);
            rx_wire<1>(a, cRx[base + 1], sRx[base + 1]);
            rx_wire<2>(a, cRx[base + 2], sRx[base + 2]);
            rx_wire<3>(a, cRx[base + 3], sRx[base + 3]);
            rx_wire<4>(a, cRx[base + 4], sRx[base + 4]);
            rx_wire<5>(a, cRx[base + 5], sRx[base + 5]);
            rx_wire<6>(a, cRx[base + 6], sRx[base + 6]);
            rx_wire<7>(a, cRx[base + 7], sRx[base + 7]);

            float p[8];
#pragma unroll
            for (int k = 0; k < 8; ++k)
                p[k] = fmaf(a[k].x, a[k].x, a[k].y * a[k].y);

            float sK = 0.f, s01 = 0.f, s12 = 0.f;
#pragma unroll
            for (int k = 0; k < 8; ++k) {
                const int pk  = __popc(k) & 1;
                const int p01 = __popc(k & 3) & 1;
                const int p12 = __popc(k >> 1) & 1;
                sK  += pk  ? -p[k] : p[k];
                s01 += p01 ? -p[k] : p[k];
                s12 += p12 ? -p[k] : p[k];
            }

            const int m3 = f4;
            const int m4 = m3 ^ f3;
            const int m5 = m4 ^ f2;
            const int m6 = m5 ^ f1;
            const int m7 = m6 ^ f0;

            z0 = m7 ? -s01 : s01;
            z1 = s12;
            z2 = sK;
            z3 = m3 ? -sK : sK;
            z4 = m4 ? -sK : sK;
            z5 = m5 ? -sK : sK;
            z6 = m6 ? -sK : sK;
            z7 = m7 ? -sK : sK;
        } else {
            float p[8];
#pragma unroll
            for (int k = 0; k < 8; ++k)
                p[k] = fmaf(a[k].x, a[k].x, a[k].y * a[k].y);
            float sA = 0.f, s0 = 0.f, s1 = 0.f, s2 = 0.f;
#pragma unroll
            for (int k = 0; k < 8; ++k) {
                sA += p[k];
                s0 += ((k >> 2) & 1) ? -p[k] : p[k];
                s1 += ((k >> 1) & 1) ? -p[k] : p[k];
                s2 += ((k     ) & 1) ? -p[k] : p[k];
            }
            z0 = s0; z1 = s1; z2 = s2;
            z3 = f4 ? -sA : sA;
            z4 = f3 ? -sA : sA;
            z5 = f2 ? -sA : sA;
            z6 = f1 ? -sA : sA;
            z7 = f0 ? -sA : sA;
        }
    }

    // ---- Reduce-scatter: 8 values over 32 lanes in 9 shuffles ----
    float K0, K1, K2, K3;
    {
        const bool b = lane & 1;
        float s0 = b ? z0 : z4;
        float s1 = b ? z1 : z5;
        float s2 = b ? z2 : z6;
        float s3 = b ? z3 : z7;
        K0 = (b ? z4 : z0) + __shfl_xor_sync(FULL, s0, 1);
        K1 = (b ? z5 : z1) + __shfl_xor_sync(FULL, s1, 1);
        K2 = (b ? z6 : z2) + __shfl_xor_sync(FULL, s2, 1);
        K3 = (b ? z7 : z3) + __shfl_xor_sync(FULL, s3, 1);
    }
    float J0, J1;
    {
        const bool b = lane & 2;
        float s0 = b ? K0 : K2;
        float s1 = b ? K1 : K3;
        J0 = (b ? K2 : K0) + __shfl_xor_sync(FULL, s0, 2);
        J1 = (b ? K3 : K1) + __shfl_xor_sync(FULL, s1, 2);
    }
    float T;
    {
        const bool b = lane & 4;
        float s0 = b ? J0 : J1;
        T = (b ? J1 : J0) + __shfl_xor_sync(FULL, s0, 4);
    }
    T += __shfl_xor_sync(FULL, T, 8);
    T += __shfl_xor_sync(FULL, T, 16);

    if (lane < 8) {
        const int v = ((lane & 1) << 2) | (lane & 2) | ((lane >> 2) & 1);
        qs[h * 8 + v] = T;
    }
    __syncthreads();

    // ---- Combine (coalesced): warp h computes out[bs, 8h .. 8h+8) ----
    const float4* W4 = reinterpret_cast<const float4*>(Wc + h * 512);
    const float4* q4 = reinterpret_cast<const float4*>(qs);

    float acc[4];
#pragma unroll
    for (int i = 0; i < 4; ++i) {
        const int c = i * 32 + lane;
        const float4 wv = W4[c];
        const float4 qv = q4[c & 15];
        acc[i] = fmaf(qv.x, wv.x,
                 fmaf(qv.y, wv.y,
                 fmaf(qv.z, wv.z, qv.w * wv.w)));
    }
#pragma unroll
    for (int off = 1; off <= 8; off <<= 1) {
#pragma unroll
        for (int i = 0; i < 4; ++i)
            acc[i] += __shfl_xor_sync(FULL, acc[i], off);
    }

    if ((lane & 15) == 0) {
        float* o = out + bs * 64 + h * 8 + (lane >> 4);  // e = 2i + (lane>>4)
        o[0] = acc[0];
        o[2] = acc[1];
        o[4] = acc[2];
        o[6] = acc[3];
    }
}

// ---------------------------------------------------------------------------
extern "C" void kernel_launch(void* const* d_in, const int* in_sizes, int n_in,
                              void* d_out, int out_size)
{
    const float* x    = (const float*)d_in[0];      // [B,S,64]
    const float* prx  = (const float*)d_in[1];      // [depth,8]
    const float* prz  = (const float*)d_in[2];      // [depth,8]
    const float* W    = (const float*)d_in[3];      // [64,64]
    float* out        = (float*)d_out;              // [B,S,64]

    const int BS    = in_sizes[0] / 64;             // 2048
    const int depth = in_sizes[1] / 8;              // 2

    if (depth == 2)
        fused_kernel<true><<<BS, 256>>>(x, prx, prz, W, out, depth);
    else
        fused_kernel<false><<<BS, 256>>>(x, prx, prz, W, out, depth);
}